// round 3
// baseline (speedup 1.0000x reference)
#include <cuda_runtime.h>
#include <math_constants.h>

// Problem constants (from reference: NB, LQ, LK, DK, DV = 16, 384, 384, 64, 64)
#define NB 16
#define LQ 384
#define LK 384
#define DK 64
#define DV 64
#define QT 32            // q-rows per block in the attn kernel
#define INV_TEMP 0.125f  // 1 / TEMPERATURE, TEMPERATURE = 8.0

// Scratch for attn probabilities in case the harness output only holds `output`.
// (No cudaMalloc allowed; __device__ global is the sanctioned workaround.)
__device__ float g_attn_scratch[NB * LQ * LK];

// ---------------------------------------------------------------------------
// Kernel A: attn[n,q,k] = softmax_k( (q[n,q,:] . k[n,k,:]) / 8 )
// grid = (LQ/QT, NB), block = 384 threads (one thread per k index).
// Each thread holds its K-row in 16 float4 registers and dots it against the
// 32 q-rows staged in shared memory (broadcast reads). Then one warp per
// q-row does the softmax over 384 scores held in shared memory.
// ---------------------------------------------------------------------------
__global__ __launch_bounds__(LK, 2)
void attn_kernel(const float* __restrict__ q,
                 const float* __restrict__ k,
                 float* __restrict__ attn_ext)
{
    __shared__ float qs[QT][DK];        // 8 KB
    __shared__ float scores[QT][LK];    // 48 KB

    float* attn = attn_ext ? attn_ext : g_attn_scratch;

    const int n  = blockIdx.y;
    const int q0 = blockIdx.x * QT;
    const int tid = threadIdx.x;        // 0..383, == k index within batch row set

    // Stage the 32 q-rows into shared memory (coalesced).
    {
        const float* qbase = q + ((size_t)n * LQ + q0) * DK;
        for (int i = tid; i < QT * DK; i += LK) {
            qs[i / DK][i % DK] = qbase[i];
        }
    }
    __syncthreads();

    // Load this thread's K-row into registers (16 x float4 = 64 floats).
    float4 kr[16];
    {
        const float4* krow = reinterpret_cast<const float4*>(
            k + ((size_t)n * LK + tid) * DK);
#pragma unroll
        for (int i = 0; i < 16; i++) kr[i] = krow[i];
    }

    // 32 dot products of length 64, q operand broadcast from shared.
    for (int qi = 0; qi < QT; qi++) {
        const float4* qrow = reinterpret_cast<const float4*>(qs[qi]);
        float acc = 0.0f;
#pragma unroll
        for (int i = 0; i < 16; i++) {
            float4 a = qrow[i];
            acc += a.x * kr[i].x + a.y * kr[i].y + a.z * kr[i].z + a.w * kr[i].w;
        }
        scores[qi][tid] = acc * INV_TEMP;
    }
    __syncthreads();

    // Softmax: warp w handles q-rows w, w+12, w+24 (12 warps, QT=32 rows -> rows
    // are covered since 12*3 >= 32; loop guards handle the remainder).
    const int warp = tid >> 5;
    const int lane = tid & 31;
    for (int qi = warp; qi < QT; qi += 12) {
        const float* row = scores[qi];

        // Row max (384 elems, 12 per lane).
        float m = -CUDART_INF_F;
#pragma unroll
        for (int j = 0; j < LK / 32; j++) m = fmaxf(m, row[lane + j * 32]);
#pragma unroll
        for (int s = 16; s > 0; s >>= 1)
            m = fmaxf(m, __shfl_xor_sync(0xFFFFFFFFu, m, s));

        // exp and sum.
        float e[LK / 32];
        float sum = 0.0f;
#pragma unroll
        for (int j = 0; j < LK / 32; j++) {
            e[j] = __expf(row[lane + j * 32] - m);
            sum += e[j];
        }
#pragma unroll
        for (int s = 16; s > 0; s >>= 1)
            sum += __shfl_xor_sync(0xFFFFFFFFu, sum, s);
        const float inv = 1.0f / sum;

        float* arow = attn + ((size_t)n * LQ + q0 + qi) * LK;
#pragma unroll
        for (int j = 0; j < LK / 32; j++)
            arow[lane + j * 32] = e[j] * inv;
    }
}

// ---------------------------------------------------------------------------
// Kernel B: out[n,q,d] = sum_k attn[n,q,k] * rel_pos_v[n,q,k,d]
// grid = NB*LQ blocks (one per (n,q)), 256 threads.
// Thread t owns (kk = t>>4, d4 = t&15): it streams rel_pos_v rows
// k = kk, kk+16, ... as float4s (fully coalesced, 24 independent LDG.128),
// then a shared-memory tree reduction folds the 16 k-slices per d4.
// This kernel is the DRAM-roofline stream of the 604 MB rel_pos_v tensor.
// ---------------------------------------------------------------------------
__global__ __launch_bounds__(256, 8)
void out_kernel(const float* __restrict__ attn_ext_is_null_marker, // unused typing aid
                const float* __restrict__ rpv,
                float* __restrict__ out,
                const float* __restrict__ attn_ext)
{
    __shared__ float  sa[LK];       // attn row, 1.5 KB
    __shared__ float4 rbuf[256];    // reduction buffer, 4 KB

    const float* attn = attn_ext ? attn_ext : g_attn_scratch;

    const int nq  = blockIdx.x;            // n*LQ + q
    const int tid = threadIdx.x;

    // Stage attn row.
    {
        const float* arow = attn + (size_t)nq * LK;
        for (int j = tid; j < LK; j += 256) sa[j] = arow[j];
    }
    __syncthreads();

    const int d4 = tid & 15;   // float4 column (d = 4*d4 .. 4*d4+3)
    const int kk = tid >> 4;   // k-slice start (k = kk, kk+16, ...)

    const float4* base = reinterpret_cast<const float4*>(
        rpv + (size_t)nq * LK * DV);

    float4 acc = make_float4(0.f, 0.f, 0.f, 0.f);
#pragma unroll
    for (int i = 0; i < LK / 16; i++) {          // 24 iterations
        const int kidx = kk + i * 16;
        const float  a = sa[kidx];
        const float4 v = base[kidx * (DV / 4) + d4];
        acc.x += a * v.x;
        acc.y += a * v.y;
        acc.z += a * v.z;
        acc.w += a * v.w;
    }

    rbuf[tid] = acc;
    __syncthreads();

    // Tree reduce over the 16 k-slices (strides 128,64,32,16 keep d4 fixed).
#pragma unroll
    for (int s = 128; s >= 16; s >>= 1) {
        if (tid < s) {
            float4 a = rbuf[tid];
            float4 b = rbuf[tid + s];
            a.x += b.x; a.y += b.y; a.z += b.z; a.w += b.w;
            rbuf[tid] = a;
        }
        __syncthreads();
    }

    // rbuf[0..15] laid out as floats is exactly out[nq, 0..63].
    if (tid < DV) {
        out[(size_t)nq * DV + tid] = reinterpret_cast<const float*>(rbuf)[tid];
    }
}

// ---------------------------------------------------------------------------
// Launch. Inputs (metadata order) = q, k, v, rel_pos, rel_pos_v.
// v and rel_pos are unused by the reference — never touched.
// Output layout assumed: [output (NB*LQ*DV) | attn (NB*LQ*LK)] flattened,
// matching the reference's (output, attn) tuple. If out_size only covers
// `output`, attn goes to the __device__ scratch instead.
// ---------------------------------------------------------------------------
extern "C" void kernel_launch(void* const* d_in, const int* in_sizes, int n_in,
                              void* d_out, int out_size)
{
    const float* q   = (const float*)d_in[0];
    const float* k   = (const float*)d_in[1];
    const float* rpv = (const float*)d_in[4];
    float* out = (float*)d_out;

    const long long out_elems  = (long long)NB * LQ * DV;   // 393216
    const long long attn_elems = (long long)NB * LQ * LK;   // 2359296

    float* attn_ext = nullptr;  // null -> kernels fall back to g_attn_scratch
    if ((long long)out_size >= out_elems + attn_elems) {
        attn_ext = out + out_elems;
    }

    dim3 gridA(LQ / QT, NB);
    attn_kernel<<<gridA, LK>>>(q, k, attn_ext);

    out_kernel<<<NB * LQ, 256>>>(nullptr, rpv, out, attn_ext);
}